// round 4
// baseline (speedup 1.0000x reference)
#include <cuda_runtime.h>
#include <math.h>

// ---------------------------------------------------------------------------
// BLSTM: B=128, S=512, H=1024, VOCAB=128
// inputs: x, h_f, h_b, c_f, c_b, emb, W_f, b_f, W_b, b_b, W_out, b_out
// output: [logits (B,S,V) | hf (B,H) | hb | cf | cb]  (fp32)
//
// Strategy: x-projection collapses to a 128-entry LUT (VOCAB=128).
// Recurrence runs in ONE persistent kernel (128 CTAs, grid barrier) to keep
// the CUDA graph tiny (5 nodes) and kill per-step launch overhead.
// ---------------------------------------------------------------------------

#define Bsz   128
#define Ssz   512
#define Hsz   1024
#define Vsz   128
#define G4    4096     // 4*H
#define KT    32
#define NB    128      // persistent grid size (1 CTA/SM, single wave on 148 SMs)

typedef unsigned long long u64;

// ------------------------- device scratch (no mallocs) ---------------------
__device__ float g_token_gates[2][Vsz][G4];          // 4 MB  : LUT (x@W + bias)
__device__ float g_partial[2][2][Bsz][G4];           // 16 MB : [ksplit][dir] split-K partials
__device__ float g_h[2][Bsz][Hsz];                   // 1 MB  : hidden state
__device__ float g_c[2][Bsz][Hsz];                   // 1 MB  : cell state
__device__ float g_out[2][Ssz][Bsz][Hsz];            // 536 MB: h history (both dirs)

__device__ volatile unsigned g_gen;                  // barrier generation
__device__ unsigned g_count;                         // barrier arrival count

// ------------------------- grid barrier ------------------------------------
// Classic fence-cumulative release/acquire barrier. All NB CTAs are resident
// (1 CTA/SM, single wave) so the spin cannot deadlock. g_gen monotonically
// increases across steps and across graph replays; g_count returns to 0.
__device__ __forceinline__ void grid_barrier()
{
    __syncthreads();
    if (threadIdx.x == 0) {
        unsigned gen = g_gen;
        __threadfence();                       // release CTA's prior writes
        unsigned t = atomicAdd(&g_count, 1);
        if (t == NB - 1) {
            g_count = 0;                       // all arrived; safe to reset
            __threadfence();
            g_gen = gen + 1;                   // release
        } else {
            while (g_gen == gen) {}
        }
        __threadfence();                       // acquire other CTAs' writes
    }
    __syncthreads();
}

// ------------------------- f32x2 packed-FMA GEMM core ----------------------
// C_tile(128x128) += A(128xK) @ B(KxN128).  256 threads, micro-tile 8x8.
__device__ __forceinline__ void gemm_tile_K(
    const float* __restrict__ A, int lda,
    const float* __restrict__ B, int ldb,
    int K, u64 acc[8][4],
    float* As, float* Bs)
{
    const int tid = threadIdx.x;
    const int tx  = tid & 15;     // column group (8 cols each)
    const int ty  = tid >> 4;     // row group    (8 rows each)

    float4 ra[4], rb[4];
#pragma unroll
    for (int i = 0; i < 4; i++) {
        int c = tid + 256 * i;
        ra[i] = *(const float4*)(A + (size_t)(c >> 3) * lda + ((c & 7) << 2));
        rb[i] = *(const float4*)(B + (size_t)(c >> 5) * ldb + ((c & 31) << 2));
    }

    for (int k0 = 0; k0 < K; k0 += KT) {
        __syncthreads();
#pragma unroll
        for (int i = 0; i < 4; i++) {
            int c = tid + 256 * i;
            *(float4*)(As + (c >> 3) * KT  + ((c & 7)  << 2)) = ra[i];
            *(float4*)(Bs + (c >> 5) * 128 + ((c & 31) << 2)) = rb[i];
        }
        __syncthreads();

        const int k1 = k0 + KT;
        if (k1 < K) {  // register prefetch of next tile overlaps FMA loop
#pragma unroll
            for (int i = 0; i < 4; i++) {
                int c = tid + 256 * i;
                ra[i] = *(const float4*)(A + (size_t)(c >> 3) * lda + k1 + ((c & 7) << 2));
                rb[i] = *(const float4*)(B + (size_t)(k1 + (c >> 5)) * ldb + ((c & 31) << 2));
            }
        }

#pragma unroll
        for (int k = 0; k < KT; k++) {
            const float* brow = Bs + k * 128 + tx * 8;
            ulonglong2 q0 = *(const ulonglong2*)brow;
            ulonglong2 q1 = *(const ulonglong2*)(brow + 4);
            u64 bp0 = q0.x, bp1 = q0.y, bp2 = q1.x, bp3 = q1.y;
#pragma unroll
            for (int i = 0; i < 8; i++) {
                float a = As[(ty * 8 + i) * KT + k];
                u64 ad;
                asm("mov.b64 %0, {%1, %1};" : "=l"(ad) : "f"(a));
                asm("fma.rn.f32x2 %0, %1, %2, %0;" : "+l"(acc[i][0]) : "l"(ad), "l"(bp0));
                asm("fma.rn.f32x2 %0, %1, %2, %0;" : "+l"(acc[i][1]) : "l"(ad), "l"(bp1));
                asm("fma.rn.f32x2 %0, %1, %2, %0;" : "+l"(acc[i][2]) : "l"(ad), "l"(bp2));
                asm("fma.rn.f32x2 %0, %1, %2, %0;" : "+l"(acc[i][3]) : "l"(ad), "l"(bp3));
            }
        }
    }
}

union F4U { u64 u[2]; float4 v; };

// ------------------------- kernel: init states -----------------------------
__global__ void k_init(const float* __restrict__ h_f, const float* __restrict__ h_b,
                       const float* __restrict__ c_f, const float* __restrict__ c_b)
{
    int i = blockIdx.x * blockDim.x + threadIdx.x;
    if (i < Bsz * Hsz) {
        ((float*)g_h)[i]             = h_f[i];
        ((float*)g_h)[Bsz * Hsz + i] = h_b[i];
        ((float*)g_c)[i]             = c_f[i];
        ((float*)g_c)[Bsz * Hsz + i] = c_b[i];
    }
}

// ------------------------- kernel: token-gate LUT ---------------------------
// token_gates[dir][v][n] = bias[n] + sum_k emb[v][k] * W[k][n]   (k < H rows)
__global__ void __launch_bounds__(256) k_lut(
    const float* __restrict__ emb,
    const float* __restrict__ W_f, const float* __restrict__ b_f,
    const float* __restrict__ W_b, const float* __restrict__ b_b)
{
    __shared__ __align__(16) float As[128 * KT];
    __shared__ __align__(16) float Bs[KT * 128];
    int dir   = blockIdx.x >> 5;
    int slice = blockIdx.x & 31;
    const float* W    = dir ? W_b : W_f;
    const float* bias = dir ? b_b : b_f;

    u64 acc[8][4] = {};
    gemm_tile_K(emb, Hsz, W + slice * 128, G4, Hsz, acc, As, Bs);

    const int tx = threadIdx.x & 15, ty = threadIdx.x >> 4;
    float* C = &g_token_gates[dir][0][0] + slice * 128;
    const float* bp = bias + slice * 128 + tx * 8;
    float4 bv0 = *(const float4*)bp;
    float4 bv1 = *(const float4*)(bp + 4);
#pragma unroll
    for (int i = 0; i < 8; i++) {
        int r = ty * 8 + i;
        F4U u0; u0.u[0] = acc[i][0]; u0.u[1] = acc[i][1];
        F4U u1; u1.u[0] = acc[i][2]; u1.u[1] = acc[i][3];
        u0.v.x += bv0.x; u0.v.y += bv0.y; u0.v.z += bv0.z; u0.v.w += bv0.w;
        u1.v.x += bv1.x; u1.v.y += bv1.y; u1.v.z += bv1.z; u1.v.w += bv1.w;
        *(float4*)(C + (size_t)r * G4 + tx * 8)     = u0.v;
        *(float4*)(C + (size_t)r * G4 + tx * 8 + 4) = u1.v;
    }
}

// ------------------------- kernel: persistent recurrence --------------------
// One wave of 128 CTAs iterates all 512 steps with grid barriers.
// CTA role: dir = blk>>6, ks = (blk>>5)&1 (K-split half), slice = blk&31.
__global__ void __launch_bounds__(256) k_recurrent(
    const float* __restrict__ W_f, const float* __restrict__ W_b,
    const int* __restrict__ x)
{
    __shared__ __align__(16) float As[128 * KT];
    __shared__ __align__(16) float Bs[KT * 128];
    const int blk   = blockIdx.x;
    const int slice = blk & 31;
    const int ks    = (blk >> 5) & 1;
    const int dir   = blk >> 6;
    const int tx    = threadIdx.x & 15, ty = threadIdx.x >> 4;
    const int tid_g = blk * 256 + threadIdx.x;        // 0..32767

    const float* W    = dir ? W_b : W_f;
    const float* Bmat = W + (size_t)(Hsz + ks * 512) * G4 + slice * 128;
    const float* A    = &g_h[dir][0][0] + ks * 512;   // 128 x 512 (lda = Hsz)
    float*       C    = &g_partial[ks][dir][0][0] + slice * 128;

    for (int s = 0; s < Ssz; s++) {
        // ---- phase 1: recurrent GEMM (h @ W_h) -> partials ----
        u64 acc[8][4] = {};
        gemm_tile_K(A, Hsz, Bmat, G4, 512, acc, As, Bs);
#pragma unroll
        for (int i = 0; i < 8; i++) {
            int r = ty * 8 + i;
            F4U u0; u0.u[0] = acc[i][0]; u0.u[1] = acc[i][1];
            F4U u1; u1.u[0] = acc[i][2]; u1.u[1] = acc[i][3];
            *(float4*)(C + (size_t)r * G4 + tx * 8)     = u0.v;
            *(float4*)(C + (size_t)r * G4 + tx * 8 + 4) = u1.v;
        }

        grid_barrier();

        // ---- phase 2: pointwise LSTM update, 8 elems/thread ----
#pragma unroll
        for (int e = 0; e < 8; e++) {
            int idx  = e * (NB * 256) + tid_g;        // 0..262143
            int d2   = idx >> 17;
            int b    = (idx >> 10) & (Bsz - 1);
            int j    = idx & (Hsz - 1);
            int t    = d2 ? (Ssz - 1 - s) : s;
            int tok  = x[b * Ssz + t];

            const float* lut = g_token_gates[d2][tok];
            const float* p0  = &g_partial[0][d2][b][0];
            const float* p1  = &g_partial[1][d2][b][0];

            float zi = p0[j]          + p1[j]          + lut[j];
            float zf = p0[Hsz + j]    + p1[Hsz + j]    + lut[Hsz + j];
            float zo = p0[2*Hsz + j]  + p1[2*Hsz + j]  + lut[2*Hsz + j];
            float zg = p0[3*Hsz + j]  + p1[3*Hsz + j]  + lut[3*Hsz + j];

            float ig = 1.f / (1.f + expf(-zi));
            float fg = 1.f / (1.f + expf(-zf));
            float og = 1.f / (1.f + expf(-zo));

            float c = fg * g_c[d2][b][j] + ig * tanhf(zg);
            g_c[d2][b][j] = c;
            float h = og * tanhf(c);
            g_h[d2][b][j] = h;
            g_out[d2][t][b][j] = h;
        }

        grid_barrier();   // next step's GEMM reads updated g_h
    }
}

// ------------------------- kernel: output projection ------------------------
// logits[b][t][v] = out_f[t][b][:]@W_out[:H] + out_b[t][b][:]@W_out[H:] + b_out
__global__ void __launch_bounds__(256) k_proj(
    const float* __restrict__ W_out, const float* __restrict__ b_out,
    float* __restrict__ out)
{
    __shared__ __align__(16) float As[128 * KT];
    __shared__ __align__(16) float Bs[KT * 128];
    int t = blockIdx.x;   // 512 CTAs, one time index each (rows = batch)

    u64 acc[8][4] = {};
    gemm_tile_K(&g_out[0][t][0][0], Hsz, W_out,             Vsz, Hsz, acc, As, Bs);
    gemm_tile_K(&g_out[1][t][0][0], Hsz, W_out + Hsz * Vsz, Vsz, Hsz, acc, As, Bs);

    const int tx = threadIdx.x & 15, ty = threadIdx.x >> 4;
    float4 bv0 = *(const float4*)(b_out + tx * 8);
    float4 bv1 = *(const float4*)(b_out + tx * 8 + 4);
#pragma unroll
    for (int i = 0; i < 8; i++) {
        int b = ty * 8 + i;
        F4U u0; u0.u[0] = acc[i][0]; u0.u[1] = acc[i][1];
        F4U u1; u1.u[0] = acc[i][2]; u1.u[1] = acc[i][3];
        u0.v.x += bv0.x; u0.v.y += bv0.y; u0.v.z += bv0.z; u0.v.w += bv0.w;
        u1.v.x += bv1.x; u1.v.y += bv1.y; u1.v.z += bv1.z; u1.v.w += bv1.w;
        float* dst = out + ((size_t)b * Ssz + t) * Vsz + tx * 8;
        *(float4*)dst       = u0.v;
        *(float4*)(dst + 4) = u1.v;
    }
}

// ------------------------- kernel: final state writeback --------------------
__global__ void k_states(float* __restrict__ out)
{
    int i = blockIdx.x * blockDim.x + threadIdx.x;
    if (i < Bsz * Hsz) {
        size_t base = (size_t)Bsz * Ssz * Vsz;        // after logits
        out[base + 0 * Bsz * Hsz + i] = ((float*)g_h)[i];             // hf
        out[base + 1 * Bsz * Hsz + i] = ((float*)g_h)[Bsz * Hsz + i]; // hb
        out[base + 2 * Bsz * Hsz + i] = ((float*)g_c)[i];             // cf
        out[base + 3 * Bsz * Hsz + i] = ((float*)g_c)[Bsz * Hsz + i]; // cb
    }
}

// ---------------------------------------------------------------------------
extern "C" void kernel_launch(void* const* d_in, const int* in_sizes, int n_in,
                              void* d_out, int out_size)
{
    const int*   x     = (const int*)  d_in[0];
    const float* h_f   = (const float*)d_in[1];
    const float* h_b   = (const float*)d_in[2];
    const float* c_f   = (const float*)d_in[3];
    const float* c_b   = (const float*)d_in[4];
    const float* emb   = (const float*)d_in[5];
    const float* W_f   = (const float*)d_in[6];
    const float* b_f   = (const float*)d_in[7];
    const float* W_b   = (const float*)d_in[8];
    const float* b_b   = (const float*)d_in[9];
    const float* W_out = (const float*)d_in[10];
    const float* b_out = (const float*)d_in[11];
    float* out = (float*)d_out;

    k_init<<<512, 256>>>(h_f, h_b, c_f, c_b);
    k_lut<<<64, 256>>>(emb, W_f, b_f, W_b, b_b);
    k_recurrent<<<NB, 256>>>(W_f, W_b, x);           // all 512 steps, 1 node
    k_proj<<<512, 256>>>(W_out, b_out, out);
    if (out_size >= (int)((size_t)Bsz * Ssz * Vsz + 4 * Bsz * Hsz))
        k_states<<<512, 256>>>(out);
}

// round 6
// speedup vs baseline: 2.3327x; 2.3327x over previous
#include <cuda_runtime.h>
#include <cuda_bf16.h>
#include <math.h>
#include <stdint.h>

// ---------------------------------------------------------------------------
// BLSTM: B=128, S=512, H=1024, VOCAB=128
// Recurrence on tensor cores via base-ISA mma.sync (bf16 hi/lo 3-pass split).
// tcgen05 is NOT available (harness compiles for plain sm_103, not sm_103a).
// ---------------------------------------------------------------------------

#define Bsz   128
#define Ssz   512
#define Hsz   1024
#define Vsz   128
#define G4    4096
#define KT    32        // FFMA gemm k-tile (lut / proj kernels)
#define NB    128       // persistent grid (1 CTA/SM, single wave)

#define BUF_BYTES 49152                   // Ah 16K | Al 16K | Wh 8K | Wl 8K
#define SMEM_DYN  (2 * BUF_BYTES + 128)

typedef unsigned long long u64;
typedef unsigned int u32;

// ------------------------- device scratch (no mallocs) ----------------------
__device__ float g_token_gates[2][Vsz][G4];            // LUT, original order
__device__ float g_lutP[2][Vsz][G4];                   // LUT, gate-permuted nP
__device__ __nv_bfloat16 g_hsplit[2][2][2][Bsz][Hsz];  // [dir][parity][hi/lo][b][k]
__device__ __nv_bfloat16 g_Wt[2][2][G4][Hsz];          // [dir][hi/lo][nP][k] 32 MB
__device__ float g_out[2][Ssz][Bsz][Hsz];              // h history
__device__ float g_cfin[2][Bsz][Hsz];                  // final c
__device__ volatile unsigned g_gen;
__device__ unsigned g_count;

// ------------------------- helpers ------------------------------------------
static __device__ __forceinline__ uint32_t smem_u32(const void* p) {
    uint32_t a;
    asm("{ .reg .u64 t; cvta.to.shared.u64 t, %1; cvt.u32.u64 %0, t; }"
        : "=r"(a) : "l"(p));
    return a;
}
static __device__ __forceinline__ uint32_t swz(uint32_t o) {   // SW128 swizzle
    return o ^ ((o >> 3) & 0x70);
}
#define CPA(dst, src) \
    asm volatile("cp.async.cg.shared.global [%0], [%1], 16;" \
                 :: "r"(dst), "l"(src) : "memory")

static __device__ __forceinline__ void ldsm4(u32 r[4], u32 addr) {
    asm volatile("ldmatrix.sync.aligned.m8n8.x4.shared.b16 {%0,%1,%2,%3}, [%4];"
                 : "=r"(r[0]), "=r"(r[1]), "=r"(r[2]), "=r"(r[3]) : "r"(addr));
}
static __device__ __forceinline__ void mma_bf16(float d[4], const u32 a[4],
                                                u32 b0, u32 b1) {
    asm volatile(
        "mma.sync.aligned.m16n8k16.row.col.f32.bf16.bf16.f32 "
        "{%0,%1,%2,%3}, {%4,%5,%6,%7}, {%8,%9}, {%0,%1,%2,%3};"
        : "+f"(d[0]), "+f"(d[1]), "+f"(d[2]), "+f"(d[3])
        : "r"(a[0]), "r"(a[1]), "r"(a[2]), "r"(a[3]), "r"(b0), "r"(b1));
}

// ------------------------- grid barrier --------------------------------------
__device__ __forceinline__ void grid_barrier()
{
    __syncthreads();
    if (threadIdx.x == 0) {
        unsigned gen = g_gen;
        __threadfence();
        unsigned t = atomicAdd(&g_count, 1);
        if (t == NB - 1) {
            g_count = 0;
            __threadfence();
            g_gen = gen + 1;
        } else {
            while (g_gen == gen) {}
        }
        __threadfence();
    }
    __syncthreads();
}

// ------------------------- FFMA GEMM core (lut / proj) -----------------------
__device__ __forceinline__ void gemm_tile_K(
    const float* __restrict__ A, int lda,
    const float* __restrict__ B, int ldb,
    int K, u64 acc[8][4],
    float* As, float* Bs)
{
    const int tid = threadIdx.x;
    const int tx  = tid & 15;
    const int ty  = tid >> 4;

    float4 ra[4], rb[4];
#pragma unroll
    for (int i = 0; i < 4; i++) {
        int c = tid + 256 * i;
        ra[i] = *(const float4*)(A + (size_t)(c >> 3) * lda + ((c & 7) << 2));
        rb[i] = *(const float4*)(B + (size_t)(c >> 5) * ldb + ((c & 31) << 2));
    }

    for (int k0 = 0; k0 < K; k0 += KT) {
        __syncthreads();
#pragma unroll
        for (int i = 0; i < 4; i++) {
            int c = tid + 256 * i;
            *(float4*)(As + (c >> 3) * KT  + ((c & 7)  << 2)) = ra[i];
            *(float4*)(Bs + (c >> 5) * 128 + ((c & 31) << 2)) = rb[i];
        }
        __syncthreads();

        const int k1 = k0 + KT;
        if (k1 < K) {
#pragma unroll
            for (int i = 0; i < 4; i++) {
                int c = tid + 256 * i;
                ra[i] = *(const float4*)(A + (size_t)(c >> 3) * lda + k1 + ((c & 7) << 2));
                rb[i] = *(const float4*)(B + (size_t)(k1 + (c >> 5)) * ldb + ((c & 31) << 2));
            }
        }

#pragma unroll
        for (int k = 0; k < KT; k++) {
            const float* brow = Bs + k * 128 + tx * 8;
            ulonglong2 q0 = *(const ulonglong2*)brow;
            ulonglong2 q1 = *(const ulonglong2*)(brow + 4);
            u64 bp0 = q0.x, bp1 = q0.y, bp2 = q1.x, bp3 = q1.y;
#pragma unroll
            for (int i = 0; i < 8; i++) {
                float a = As[(ty * 8 + i) * KT + k];
                u64 ad;
                asm("mov.b64 %0, {%1, %1};" : "=l"(ad) : "f"(a));
                asm("fma.rn.f32x2 %0, %1, %2, %0;" : "+l"(acc[i][0]) : "l"(ad), "l"(bp0));
                asm("fma.rn.f32x2 %0, %1, %2, %0;" : "+l"(acc[i][1]) : "l"(ad), "l"(bp1));
                asm("fma.rn.f32x2 %0, %1, %2, %0;" : "+l"(acc[i][2]) : "l"(ad), "l"(bp2));
                asm("fma.rn.f32x2 %0, %1, %2, %0;" : "+l"(acc[i][3]) : "l"(ad), "l"(bp3));
            }
        }
    }
}

union F4U { u64 u[2]; float4 v; };

// ------------------------- prep kernels --------------------------------------
__global__ void k_hinit(const float* __restrict__ h_f, const float* __restrict__ h_b)
{
    int i = blockIdx.x * blockDim.x + threadIdx.x;
    if (i < 2 * Bsz * Hsz) {
        int dir = i >> 17, b = (i >> 10) & 127, k = i & 1023;
        float v = (dir ? h_b : h_f)[b * Hsz + k];
        __nv_bfloat16 hi = __float2bfloat16(v);
        __nv_bfloat16 lo = __float2bfloat16(v - __bfloat162float(hi));
        g_hsplit[dir][0][0][b][k] = hi;
        g_hsplit[dir][0][1][b][k] = lo;
    }
}

// W^T permuted: nP = slice*64 + g*16 + jl  <->  orig col = g*1024 + slice*16 + jl
__global__ void __launch_bounds__(256) k_wprep(const float* __restrict__ W_f,
                                               const float* __restrict__ W_b)
{
    int bid   = blockIdx.x;                 // 8192 blocks
    int kblk  = bid & 15;
    int g     = (bid >> 4) & 3;
    int slice = (bid >> 6) & 63;
    int dir   = bid >> 12;
    const float* W = dir ? W_b : W_f;

    int jl = threadIdx.x >> 4;
    int kk = threadIdx.x & 15;
    int col = g * 1024 + slice * 16 + jl;
    int nP  = slice * 64 + g * 16 + jl;
#pragma unroll
    for (int r = 0; r < 4; r++) {
        int k = kblk * 64 + kk + r * 16;
        float w = W[(size_t)(Hsz + k) * G4 + col];
        __nv_bfloat16 hi = __float2bfloat16(w);
        __nv_bfloat16 lo = __float2bfloat16(w - __bfloat162float(hi));
        g_Wt[dir][0][nP][k] = hi;
        g_Wt[dir][1][nP][k] = lo;
    }
}

__global__ void k_lutperm()
{
    int i = blockIdx.x * blockDim.x + threadIdx.x;
    if (i < 2 * Vsz * G4) {
        int d = i >> 19, v = (i >> 12) & 127, nP = i & 4095;
        int slice = nP >> 6, g = (nP >> 4) & 3, jl = nP & 15;
        g_lutP[d][v][nP] = g_token_gates[d][v][g * 1024 + slice * 16 + jl];
    }
}

__global__ void __launch_bounds__(256) k_lut(
    const float* __restrict__ emb,
    const float* __restrict__ W_f, const float* __restrict__ b_f,
    const float* __restrict__ W_b, const float* __restrict__ b_b)
{
    __shared__ __align__(16) float As[128 * KT];
    __shared__ __align__(16) float Bs[KT * 128];
    int dir   = blockIdx.x >> 5;
    int slice = blockIdx.x & 31;
    const float* W    = dir ? W_b : W_f;
    const float* bias = dir ? b_b : b_f;

    u64 acc[8][4] = {};
    gemm_tile_K(emb, Hsz, W + slice * 128, G4, Hsz, acc, As, Bs);

    const int tx = threadIdx.x & 15, ty = threadIdx.x >> 4;
    float* C = &g_token_gates[dir][0][0] + slice * 128;
    const float* bp = bias + slice * 128 + tx * 8;
    float4 bv0 = *(const float4*)bp;
    float4 bv1 = *(const float4*)(bp + 4);
#pragma unroll
    for (int i = 0; i < 8; i++) {
        int r = ty * 8 + i;
        F4U u0; u0.u[0] = acc[i][0]; u0.u[1] = acc[i][1];
        F4U u1; u1.u[0] = acc[i][2]; u1.u[1] = acc[i][3];
        u0.v.x += bv0.x; u0.v.y += bv0.y; u0.v.z += bv0.z; u0.v.w += bv0.w;
        u1.v.x += bv1.x; u1.v.y += bv1.y; u1.v.z += bv1.z; u1.v.w += bv1.w;
        *(float4*)(C + (size_t)r * G4 + tx * 8)     = u0.v;
        *(float4*)(C + (size_t)r * G4 + tx * 8 + 4) = u1.v;
    }
}

// ------------------------- persistent HMMA recurrence ------------------------
// Stage one k64 chunk (A hi/lo 128x64, W hi/lo 64x64, bf16) into smem buffer.
__device__ __forceinline__ void issue_chunk(
    uint32_t sbuf, const char* pAhi, const char* pAlo,
    const char* pW0, const char* pW1, int kc, int tid)
{
    const size_t kb = (size_t)kc * 128;
#pragma unroll
    for (int i = 0; i < 4; i++) {
        int idx = tid + 256 * i;
        int row = idx >> 3, seg = idx & 7;
        uint32_t so = swz((uint32_t)(row * 128 + seg * 16));
        const char* ga = pAhi + (size_t)row * 2048 + kb + seg * 16;
        const char* gb = pAlo + (size_t)row * 2048 + kb + seg * 16;
        CPA(sbuf + so,         ga);
        CPA(sbuf + 16384 + so, gb);
    }
#pragma unroll
    for (int i = 0; i < 2; i++) {
        int idx = tid + 256 * i;
        int row = idx >> 3, seg = idx & 7;
        uint32_t so = swz((uint32_t)(row * 128 + seg * 16));
        CPA(sbuf + 32768 + so, pW0 + (size_t)row * 2048 + kb + seg * 16);
        CPA(sbuf + 40960 + so, pW1 + (size_t)row * 2048 + kb + seg * 16);
    }
    asm volatile("cp.async.commit_group;" ::: "memory");
}

__global__ void __launch_bounds__(256, 1) k_recurrent(
    const int* __restrict__ x,
    const float* __restrict__ c_f, const float* __restrict__ c_b)
{
    extern __shared__ __align__(128) char dsm[];
    const uint32_t sb = smem_u32(dsm);

    const int tid   = threadIdx.x;
    const int w     = tid >> 5;
    const int lane  = tid & 31;
    const int lr    = lane & 15;          // ldmatrix row-provider index
    const int lh    = lane >> 4;          // which 16B half of k16
    const int q     = lane & 3;
    const int r0    = lane >> 2;
    const int blk   = blockIdx.x;
    const int dir   = blk >> 6;
    const int slice = blk & 63;
    const int n0    = slice * 64;
    const int j0    = slice * 16;

    // c state thread-local for all 512 steps:
    // ci = row01*4 + jl8*2 + jj  ->  b = w*16 + r0 + row01*8, jl = jl8*8 + 2q + jj
    float c_reg[8];
    {
        const float* cin = (dir ? c_b : c_f);
#pragma unroll
        for (int ci = 0; ci < 8; ci++) {
            int row01 = ci >> 2, jl8 = (ci >> 1) & 1, jj = ci & 1;
            int b = w * 16 + r0 + row01 * 8;
            int jl = jl8 * 8 + 2 * q + jj;
            c_reg[ci] = cin[(size_t)b * Hsz + j0 + jl];
        }
    }

    const char* pW0 = (const char*)&g_Wt[dir][0][n0][0];
    const char* pW1 = (const char*)&g_Wt[dir][1][n0][0];

    for (int s = 0; s < Ssz; s++) {
        const int rp = s & 1;
        const char* pAhi = (const char*)&g_hsplit[dir][rp][0][0][0];
        const char* pAlo = (const char*)&g_hsplit[dir][rp][1][0][0];

        float d[8][4];
#pragma unroll
        for (int t = 0; t < 8; t++)
#pragma unroll
            for (int r = 0; r < 4; r++) d[t][r] = 0.f;

        issue_chunk(sb, pAhi, pAlo, pW0, pW1, 0, tid);

        for (int kc = 0; kc < 16; kc++) {
            asm volatile("cp.async.wait_group 0;" ::: "memory");
            __syncthreads();
            if (kc < 15)
                issue_chunk(sb + ((kc + 1) & 1) * BUF_BYTES,
                            pAhi, pAlo, pW0, pW1, kc + 1, tid);

            const uint32_t base = sb + (kc & 1) * BUF_BYTES;
#pragma unroll
            for (int kk4 = 0; kk4 < 4; kk4++) {
                const uint32_t koff = kk4 * 32;
                u32 ah[4], al[4];
                uint32_t arow = swz((uint32_t)((w * 16 + lr) * 128) + koff + lh * 16);
                ldsm4(ah, base + arow);
                ldsm4(al, base + 16384 + arow);
#pragma unroll
                for (int nb = 0; nb < 4; nb++) {
                    u32 wh[4], wl[4];
                    uint32_t wrow = swz((uint32_t)((nb * 16 + lr) * 128) + koff + lh * 16);
                    ldsm4(wh, base + 32768 + wrow);
                    ldsm4(wl, base + 40960 + wrow);
                    mma_bf16(d[2 * nb],     ah, wh[0], wh[2]);
                    mma_bf16(d[2 * nb + 1], ah, wh[1], wh[3]);
                    mma_bf16(d[2 * nb],     ah, wl[0], wl[2]);
                    mma_bf16(d[2 * nb + 1], ah, wl[1], wl[3]);
                    mma_bf16(d[2 * nb],     al, wh[0], wh[2]);
                    mma_bf16(d[2 * nb + 1], al, wh[1], wh[3]);
                }
            }
        }

        // ---- epilogue: LSTM update fully thread-local ----
        const int wp = rp ^ 1;
        const int tstep = dir ? (Ssz - 1 - s) : s;
#pragma unroll
        for (int row01 = 0; row01 < 2; row01++) {
            const int b = w * 16 + r0 + row01 * 8;
            const int tok = x[b * Ssz + tstep];
            const float* lutb = &g_lutP[dir][tok][n0];
#pragma unroll
            for (int jl8 = 0; jl8 < 2; jl8++) {
                const int jb = jl8 * 8 + 2 * q;
                float2 li = *(const float2*)(lutb +      jb);
                float2 lf = *(const float2*)(lutb + 16 + jb);
                float2 lo2= *(const float2*)(lutb + 32 + jb);
                float2 lg = *(const float2*)(lutb + 48 + jb);
                float hv[2], hh[2], hl[2];
#pragma unroll
                for (int jj = 0; jj < 2; jj++) {
                    const int reg = row01 * 2 + jj;
                    const int ci  = row01 * 4 + jl8 * 2 + jj;
                    float zi = d[0 + jl8][reg] + (jj ? li.y  : li.x);
                    float zf = d[2 + jl8][reg] + (jj ? lf.y  : lf.x);
                    float zo = d[4 + jl8][reg] + (jj ? lo2.y : lo2.x);
                    float zg = d[6 + jl8][reg] + (jj ? lg.y  : lg.x);
                    float ig = 1.f / (1.f + __expf(-zi));
                    float fg = 1.f / (1.f + __expf(-zf));
                    float og = 1.f / (1.f + __expf(-zo));
                    float cc = fg * c_reg[ci] + ig * tanhf(zg);
                    c_reg[ci] = cc;
                    float h = og * tanhf(cc);
                    hv[jj] = h;
                    __nv_bfloat16 hb = __float2bfloat16(h);
                    hh[jj] = __bfloat162float(hb);
                    hl[jj] = h - hh[jj];
                }
                *(float2*)(&g_out[dir][tstep][b][j0 + jb]) = make_float2(hv[0], hv[1]);
                __nv_bfloat162 phi = __floats2bfloat162_rn(hh[0], hh[1]);
                __nv_bfloat162 plo = __floats2bfloat162_rn(hl[0], hl[1]);
                *(u32*)(&g_hsplit[dir][wp][0][b][j0 + jb]) = *(u32*)&phi;
                *(u32*)(&g_hsplit[dir][wp][1][b][j0 + jb]) = *(u32*)&plo;
            }
        }

        grid_barrier();   // publish h(s+1) before next step's A loads
    }

    // final c writeback
#pragma unroll
    for (int ci = 0; ci < 8; ci++) {
        int row01 = ci >> 2, jl8 = (ci >> 1) & 1, jj = ci & 1;
        int b = w * 16 + r0 + row01 * 8;
        int jl = jl8 * 8 + 2 * q + jj;
        g_cfin[dir][b][j0 + jl] = c_reg[ci];
    }
}

// ------------------------- output projection (FFMA) --------------------------
__global__ void __launch_bounds__(256) k_proj(
    const float* __restrict__ W_out, const float* __restrict__ b_out,
    float* __restrict__ out)
{
    __shared__ __align__(16) float As[128 * KT];
    __shared__ __align__(16) float Bs[KT * 128];
    int t = blockIdx.x;

    u64 acc[8][4] = {};
    gemm_tile_K(&g_out[0][t][0][0], Hsz, W_out,             Vsz, Hsz, acc, As, Bs);
    gemm_tile_K(&g_out[1][t][0][0], Hsz, W_out + Hsz * Vsz, Vsz, Hsz, acc, As, Bs);

    const int tx = threadIdx.x & 15, ty = threadIdx.x >> 4;
    float4 bv0 = *(const float4*)(b_out + tx * 8);
    float4 bv1 = *(const float4*)(b_out + tx * 8 + 4);
#pragma unroll
    for (int i = 0; i < 8; i++) {
        int b = ty * 8 + i;
        F4U u0; u0.u[0] = acc[i][0]; u0.u[1] = acc[i][1];
        F4U u1; u1.u[0] = acc[i][2]; u1.u[1] = acc[i][3];
        u0.v.x += bv0.x; u0.v.y += bv0.y; u0.v.z += bv0.z; u0.v.w += bv0.w;
        u1.v.x += bv1.x; u1.v.y += bv1.y; u1.v.z += bv1.z; u1.v.w += bv1.w;
        float* dst = out + ((size_t)b * Ssz + t) * Vsz + tx * 8;
        *(float4*)dst       = u0.v;
        *(float4*)(dst + 4) = u1.v;
    }
}

// ------------------------- final state writeback -----------------------------
__global__ void k_states(float* __restrict__ out)
{
    int i = blockIdx.x * blockDim.x + threadIdx.x;
    if (i < Bsz * Hsz) {
        int b = i >> 10, j = i & 1023;
        size_t base = (size_t)Bsz * Ssz * Vsz;
        out[base + 0 * Bsz * Hsz + i] = g_out[0][Ssz - 1][b][j];  // hf
        out[base + 1 * Bsz * Hsz + i] = g_out[1][0][b][j];        // hb
        out[base + 2 * Bsz * Hsz + i] = g_cfin[0][b][j];          // cf
        out[base + 3 * Bsz * Hsz + i] = g_cfin[1][b][j];          // cb
    }
}

// ---------------------------------------------------------------------------
extern "C" void kernel_launch(void* const* d_in, const int* in_sizes, int n_in,
                              void* d_out, int out_size)
{
    const int*   x     = (const int*)  d_in[0];
    const float* h_f   = (const float*)d_in[1];
    const float* h_b   = (const float*)d_in[2];
    const float* c_f   = (const float*)d_in[3];
    const float* c_b   = (const float*)d_in[4];
    const float* emb   = (const float*)d_in[5];
    const float* W_f   = (const float*)d_in[6];
    const float* b_f   = (const float*)d_in[7];
    const float* W_b   = (const float*)d_in[8];
    const float* b_b   = (const float*)d_in[9];
    const float* W_out = (const float*)d_in[10];
    const float* b_out = (const float*)d_in[11];
    float* out = (float*)d_out;

    static bool attr_done = false;
    if (!attr_done) {
        cudaFuncSetAttribute(k_recurrent,
                             cudaFuncAttributeMaxDynamicSharedMemorySize, SMEM_DYN);
        attr_done = true;
    }

    k_hinit<<<1024, 256>>>(h_f, h_b);
    k_wprep<<<8192, 256>>>(W_f, W_b);
    k_lut<<<64, 256>>>(emb, W_f, b_f, W_b, b_b);
    k_lutperm<<<4096, 256>>>();

    k_recurrent<<<NB, 256, SMEM_DYN>>>(x, c_f, c_b);

    k_proj<<<512, 256>>>(W_out, b_out, out);
    if (out_size >= (int)((size_t)Bsz * Ssz * Vsz + 4 * Bsz * Hsz))
        k_states<<<512, 256>>>(out);
}

// round 7
// speedup vs baseline: 3.2715x; 1.4025x over previous
#include <cuda_runtime.h>
#include <cuda_fp16.h>
#include <math.h>
#include <stdint.h>

// ---------------------------------------------------------------------------
// BLSTM: B=128, S=512, H=1024, VOCAB=128
// fp16 2-product HMMA recurrence (h fp16, W fp16 hi + scaled lo, fp32 acc),
// m32n32 warp tiles, k128 chunks, HMMA output projection.
// ---------------------------------------------------------------------------

#define Bsz   128
#define Ssz   512
#define Hsz   1024
#define Vsz   128
#define G4    4096
#define KT    32
#define NB    128

#define SC_W  2048.0f
#define SC_WI (1.0f/2048.0f)

// buffer: A 32K | Wh 16K | Wl 16K = 64 KB ; double buffered = 128 KB
#define RBUF      65536
#define SMEM_DYN  (2 * RBUF)

typedef unsigned long long u64;
typedef unsigned int u32;

// ------------------------- device scratch -----------------------------------
__device__ float  g_token_gates[2][Vsz][G4];       // LUT original order
__device__ float  g_lutP[2][Vsz][G4];              // LUT permuted (nP)
__device__ __half g_h16[2][2][Bsz][Hsz];           // [dir][parity][b][k]
__device__ __half g_Wh[2][G4][Hsz];                // W^T hi (permuted nP)
__device__ __half g_Wl[2][G4][Hsz];                // W^T lo * SC_W
__device__ __half g_out16[2][Ssz][Bsz][Hsz];       // h history fp16 (268 MB)
__device__ __half g_WoTh[Vsz][2 * Hsz];            // W_out^T hi
__device__ __half g_WoTl[Vsz][2 * Hsz];            // W_out^T lo * SC_W
__device__ float  g_hfin[2][Bsz][Hsz];
__device__ float  g_cfin[2][Bsz][Hsz];
__device__ volatile unsigned g_gen;
__device__ unsigned g_count;

// ------------------------- helpers ------------------------------------------
static __device__ __forceinline__ uint32_t smem_u32(const void* p) {
    uint32_t a;
    asm("{ .reg .u64 t; cvta.to.shared.u64 t, %1; cvt.u32.u64 %0, t; }"
        : "=r"(a) : "l"(p));
    return a;
}
static __device__ __forceinline__ uint32_t swz(uint32_t o) {
    return o ^ ((o >> 3) & 0x70);
}
#define CPA(dst, src) \
    asm volatile("cp.async.cg.shared.global [%0], [%1], 16;" \
                 :: "r"(dst), "l"(src) : "memory")

static __device__ __forceinline__ void ldsm4(u32 r[4], u32 addr) {
    asm volatile("ldmatrix.sync.aligned.m8n8.x4.shared.b16 {%0,%1,%2,%3}, [%4];"
                 : "=r"(r[0]), "=r"(r[1]), "=r"(r[2]), "=r"(r[3]) : "r"(addr));
}
static __device__ __forceinline__ void mma_f16(float d[4], const u32 a[4],
                                               u32 b0, u32 b1) {
    asm volatile(
        "mma.sync.aligned.m16n8k16.row.col.f32.f16.f16.f32 "
        "{%0,%1,%2,%3}, {%4,%5,%6,%7}, {%8,%9}, {%0,%1,%2,%3};"
        : "+f"(d[0]), "+f"(d[1]), "+f"(d[2]), "+f"(d[3])
        : "r"(a[0]), "r"(a[1]), "r"(a[2]), "r"(a[3]), "r"(b0), "r"(b1));
}

// ------------------------- grid barrier --------------------------------------
__device__ __forceinline__ void grid_barrier()
{
    __syncthreads();
    if (threadIdx.x == 0) {
        unsigned gen = g_gen;
        __threadfence();
        unsigned t = atomicAdd(&g_count, 1);
        if (t == NB - 1) {
            g_count = 0;
            __threadfence();
            g_gen = gen + 1;
        } else {
            while (g_gen == gen) {}
        }
        __threadfence();
    }
    __syncthreads();
}

// ------------------------- FFMA GEMM core (lut only) -------------------------
__device__ __forceinline__ void gemm_tile_K(
    const float* __restrict__ A, int lda,
    const float* __restrict__ B, int ldb,
    int K, u64 acc[8][4],
    float* As, float* Bs)
{
    const int tid = threadIdx.x;
    const int tx  = tid & 15;
    const int ty  = tid >> 4;

    float4 ra[4], rb[4];
#pragma unroll
    for (int i = 0; i < 4; i++) {
        int c = tid + 256 * i;
        ra[i] = *(const float4*)(A + (size_t)(c >> 3) * lda + ((c & 7) << 2));
        rb[i] = *(const float4*)(B + (size_t)(c >> 5) * ldb + ((c & 31) << 2));
    }
    for (int k0 = 0; k0 < K; k0 += KT) {
        __syncthreads();
#pragma unroll
        for (int i = 0; i < 4; i++) {
            int c = tid + 256 * i;
            *(float4*)(As + (c >> 3) * KT  + ((c & 7)  << 2)) = ra[i];
            *(float4*)(Bs + (c >> 5) * 128 + ((c & 31) << 2)) = rb[i];
        }
        __syncthreads();
        const int k1 = k0 + KT;
        if (k1 < K) {
#pragma unroll
            for (int i = 0; i < 4; i++) {
                int c = tid + 256 * i;
                ra[i] = *(const float4*)(A + (size_t)(c >> 3) * lda + k1 + ((c & 7) << 2));
                rb[i] = *(const float4*)(B + (size_t)(k1 + (c >> 5)) * ldb + ((c & 31) << 2));
            }
        }
#pragma unroll
        for (int k = 0; k < KT; k++) {
            const float* brow = Bs + k * 128 + tx * 8;
            ulonglong2 q0 = *(const ulonglong2*)brow;
            ulonglong2 q1 = *(const ulonglong2*)(brow + 4);
            u64 bp0 = q0.x, bp1 = q0.y, bp2 = q1.x, bp3 = q1.y;
#pragma unroll
            for (int i = 0; i < 8; i++) {
                float a = As[(ty * 8 + i) * KT + k];
                u64 ad;
                asm("mov.b64 %0, {%1, %1};" : "=l"(ad) : "f"(a));
                asm("fma.rn.f32x2 %0, %1, %2, %0;" : "+l"(acc[i][0]) : "l"(ad), "l"(bp0));
                asm("fma.rn.f32x2 %0, %1, %2, %0;" : "+l"(acc[i][1]) : "l"(ad), "l"(bp1));
                asm("fma.rn.f32x2 %0, %1, %2, %0;" : "+l"(acc[i][2]) : "l"(ad), "l"(bp2));
                asm("fma.rn.f32x2 %0, %1, %2, %0;" : "+l"(acc[i][3]) : "l"(ad), "l"(bp3));
            }
        }
    }
}
union F4U { u64 u[2]; float4 v; };

// ------------------------- prep kernels --------------------------------------
__global__ void k_hinit(const float* __restrict__ h_f, const float* __restrict__ h_b)
{
    int i = blockIdx.x * blockDim.x + threadIdx.x;
    if (i < 2 * Bsz * Hsz) {
        int dir = i >> 17, b = (i >> 10) & 127, k = i & 1023;
        g_h16[dir][0][b][k] = __float2half((dir ? h_b : h_f)[b * Hsz + k]);
    }
}

// nP = slice*64 + jh*32 + g*8 + jl3  <->  orig col = g*1024 + slice*16 + jh*8 + jl3
__global__ void __launch_bounds__(256) k_wprep(const float* __restrict__ W_f,
                                               const float* __restrict__ W_b)
{
    int bid   = blockIdx.x;                 // 8192 blocks
    int kblk  = bid & 15;
    int g     = (bid >> 4) & 3;
    int slice = (bid >> 6) & 63;
    int dir   = bid >> 12;
    const float* W = dir ? W_b : W_f;

    int jl = threadIdx.x >> 4;              // 0..15
    int kk = threadIdx.x & 15;
    int col = g * 1024 + slice * 16 + jl;
    int jh = jl >> 3, jl3 = jl & 7;
    int nP  = slice * 64 + jh * 32 + g * 8 + jl3;
#pragma unroll
    for (int r = 0; r < 4; r++) {
        int k = kblk * 64 + kk + r * 16;
        float w = W[(size_t)(Hsz + k) * G4 + col];
        __half hi = __float2half(w);
        g_Wh[dir][nP][k] = hi;
        g_Wl[dir][nP][k] = __float2half((w - __half2float(hi)) * SC_W);
    }
}

__global__ void k_lutperm()
{
    int i = blockIdx.x * blockDim.x + threadIdx.x;
    if (i < 2 * Vsz * G4) {
        int d = i >> 19, v = (i >> 12) & 127, nP = i & 4095;
        int slice = nP >> 6, rem = nP & 63;
        int jh = rem >> 5, g = (rem >> 3) & 3, jl3 = rem & 7;
        g_lutP[d][v][nP] =
            g_token_gates[d][v][g * 1024 + slice * 16 + jh * 8 + jl3];
    }
}

__global__ void k_woutprep(const float* __restrict__ W_out)
{
    int i = blockIdx.x * blockDim.x + threadIdx.x;
    if (i < Vsz * 2 * Hsz) {
        int v = i >> 11, k = i & 2047;
        float wv = W_out[(size_t)k * Vsz + v];
        __half hi = __float2half(wv);
        g_WoTh[v][k] = hi;
        g_WoTl[v][k] = __float2half((wv - __half2float(hi)) * SC_W);
    }
}

__global__ void __launch_bounds__(256) k_lut(
    const float* __restrict__ emb,
    const float* __restrict__ W_f, const float* __restrict__ b_f,
    const float* __restrict__ W_b, const float* __restrict__ b_b)
{
    __shared__ __align__(16) float As[128 * KT];
    __shared__ __align__(16) float Bs[KT * 128];
    int dir   = blockIdx.x >> 5;
    int slice = blockIdx.x & 31;
    const float* W    = dir ? W_b : W_f;
    const float* bias = dir ? b_b : b_f;

    u64 acc[8][4] = {};
    gemm_tile_K(emb, Hsz, W + slice * 128, G4, Hsz, acc, As, Bs);

    const int tx = threadIdx.x & 15, ty = threadIdx.x >> 4;
    float* C = &g_token_gates[dir][0][0] + slice * 128;
    float4 bv0 = *(const float4*)(bias + slice * 128 + tx * 8);
    float4 bv1 = *(const float4*)(bias + slice * 128 + tx * 8 + 4);
#pragma unroll
    for (int i = 0; i < 8; i++) {
        int r = ty * 8 + i;
        F4U u0; u0.u[0] = acc[i][0]; u0.u[1] = acc[i][1];
        F4U u1; u1.u[0] = acc[i][2]; u1.u[1] = acc[i][3];
        u0.v.x += bv0.x; u0.v.y += bv0.y; u0.v.z += bv0.z; u0.v.w += bv0.w;
        u1.v.x += bv1.x; u1.v.y += bv1.y; u1.v.z += bv1.z; u1.v.w += bv1.w;
        *(float4*)(C + (size_t)r * G4 + tx * 8)     = u0.v;
        *(float4*)(C + (size_t)r * G4 + tx * 8 + 4) = u1.v;
    }
}

// ------------------------- k128 chunk staging --------------------------------
// buffer layout: A[kh2][128 rows x 128B] | Wh[kh2][64 x 128B] | Wl same
__device__ __forceinline__ void rec_issue(uint32_t buf, const char* pA,
    const char* pWh, const char* pWl, size_t kb, int tid)
{
#pragma unroll
    for (int i = 0; i < 8; i++) {
        int idx = tid + 256 * i;
        int kh = idx >> 10, r = (idx >> 3) & 127, seg = idx & 7;
        CPA(buf + kh * 16384 + swz(r * 128 + seg * 16),
            pA + (size_t)r * 2048 + kb + kh * 128 + seg * 16);
    }
#pragma unroll
    for (int i = 0; i < 4; i++) {
        int idx = tid + 256 * i;
        int kh = idx >> 9, r = (idx >> 3) & 63, seg = idx & 7;
        uint32_t so = kh * 8192 + swz(r * 128 + seg * 16);
        size_t go = (size_t)r * 2048 + kb + kh * 128 + seg * 16;
        CPA(buf + 32768 + so, pWh + go);
        CPA(buf + 49152 + so, pWl + go);
    }
    asm volatile("cp.async.commit_group;" ::: "memory");
}

// shared math for one k128 chunk (m32n32 warp tile, 2 products)
#define CHUNK_MATH(base)                                                        \
    _Pragma("unroll")                                                           \
    for (int kk = 0; kk < 8; kk++) {                                            \
        const int kh = kk >> 2;                                                 \
        const uint32_t koff = (kk & 3) * 32 + lh * 16;                          \
        const uint32_t ab = (base) + kh * 16384;                                \
        u32 ah0[4], ah1[4];                                                     \
        ldsm4(ah0, ab + swz((mrow * 32 + lr) * 128 + koff));                    \
        ldsm4(ah1, ab + swz((mrow * 32 + 16 + lr) * 128 + koff));               \
        const uint32_t wb = (base) + 32768 + kh * 8192;                         \
        _Pragma("unroll")                                                       \
        for (int nh = 0; nh < 2; nh++) {                                        \
            u32 wh[4], wl[4];                                                   \
            uint32_t wro = swz((ncol * 32 + nh * 16 + lr) * 128 + koff);        \
            ldsm4(wh, wb + wro);                                                \
            ldsm4(wl, wb + 16384 + wro);                                        \
            mma_f16(d1[nh * 2],     ah0, wh[0], wh[2]);                         \
            mma_f16(d1[nh * 2 + 1], ah0, wh[1], wh[3]);                         \
            mma_f16(d2[nh * 2],     ah0, wl[0], wl[2]);                         \
            mma_f16(d2[nh * 2 + 1], ah0, wl[1], wl[3]);                         \
            mma_f16(d1[4 + nh * 2],     ah1, wh[0], wh[2]);                     \
            mma_f16(d1[4 + nh * 2 + 1], ah1, wh[1], wh[3]);                     \
            mma_f16(d2[4 + nh * 2],     ah1, wl[0], wl[2]);                     \
            mma_f16(d2[4 + nh * 2 + 1], ah1, wl[1], wl[3]);                     \
        }                                                                       \
    }

// ------------------------- persistent recurrence -----------------------------
__global__ void __launch_bounds__(256, 1) k_recurrent(
    const int* __restrict__ x,
    const float* __restrict__ c_f, const float* __restrict__ c_b)
{
    extern __shared__ __align__(128) char dsm[];
    const uint32_t sb = smem_u32(dsm);

    const int tid  = threadIdx.x;
    const int w    = tid >> 5, lane = tid & 31;
    const int lr   = lane & 15, lh = lane >> 4;
    const int q    = lane & 3,  r0 = lane >> 2;
    const int blk  = blockIdx.x;
    const int dir  = blk >> 6, slice = blk & 63;
    const int n0   = slice * 64, j0 = slice * 16;
    const int mrow = w >> 1, ncol = w & 1;

    float c_reg[8];
    {
        const float* cin = dir ? c_b : c_f;
#pragma unroll
        for (int ci = 0; ci < 8; ci++) {
            int mt = ci >> 2, rr = (ci >> 1) & 1, jj = ci & 1;
            int b  = mrow * 32 + mt * 16 + rr * 8 + r0;
            int jl = ncol * 8 + 2 * q + jj;
            c_reg[ci] = cin[(size_t)b * Hsz + j0 + jl];
        }
    }

    const char* pWh = (const char*)&g_Wh[dir][n0][0];
    const char* pWl = (const char*)&g_Wl[dir][n0][0];

    for (int s = 0; s < Ssz; s++) {
        const int rp = s & 1;
        const char* pA = (const char*)&g_h16[dir][rp][0][0];

        float d1[8][4] = {}, d2[8][4] = {};
        rec_issue(sb, pA, pWh, pWl, 0, tid);

        for (int kc = 0; kc < 8; kc++) {
            asm volatile("cp.async.wait_group 0;" ::: "memory");
            __syncthreads();
            if (kc < 7)
                rec_issue(sb + ((kc + 1) & 1) * RBUF, pA, pWh, pWl,
                          (size_t)(kc + 1) * 256, tid);
            const uint32_t base = sb + (kc & 1) * RBUF;
            CHUNK_MATH(base)
        }

        // ---- epilogue: thread-local LSTM update ----
        const int wp = rp ^ 1;
        const int ts = dir ? (Ssz - 1 - s) : s;
#pragma unroll
        for (int mt = 0; mt < 2; mt++) {
#pragma unroll
            for (int rr = 0; rr < 2; rr++) {
                const int b = mrow * 32 + mt * 16 + rr * 8 + r0;
                const int tok = x[b * Ssz + ts];
                const float* lutb = &g_lutP[dir][tok][n0 + ncol * 32];
                float2 l0 = *(const float2*)(lutb +  0 + 2 * q);
                float2 l1 = *(const float2*)(lutb +  8 + 2 * q);
                float2 l2 = *(const float2*)(lutb + 16 + 2 * q);
                float2 l3 = *(const float2*)(lutb + 24 + 2 * q);
                float hv[2];
#pragma unroll
                for (int jj = 0; jj < 2; jj++) {
                    const int ri = rr * 2 + jj;
                    float zi = d1[mt*4+0][ri] + d2[mt*4+0][ri] * SC_WI + (jj ? l0.y : l0.x);
                    float zf = d1[mt*4+1][ri] + d2[mt*4+1][ri] * SC_WI + (jj ? l1.y : l1.x);
                    float zo = d1[mt*4+2][ri] + d2[mt*4+2][ri] * SC_WI + (jj ? l2.y : l2.x);
                    float zg = d1[mt*4+3][ri] + d2[mt*4+3][ri] * SC_WI + (jj ? l3.y : l3.x);
                    float ig = 1.f / (1.f + __expf(-zi));
                    float fg = 1.f / (1.f + __expf(-zf));
                    float og = 1.f / (1.f + __expf(-zo));
                    const int ci = mt * 4 + rr * 2 + jj;
                    float cc = fg * c_reg[ci] + ig * tanhf(zg);
                    c_reg[ci] = cc;
                    hv[jj] = og * tanhf(cc);
                }
                __half2 hp = __floats2half2_rn(hv[0], hv[1]);
                const int jcol = j0 + ncol * 8 + 2 * q;
                *(u32*)(&g_h16[dir][wp][b][jcol])   = *(u32*)&hp;
                *(u32*)(&g_out16[dir][ts][b][jcol]) = *(u32*)&hp;
                if (s == Ssz - 1)
                    *(float2*)(&g_hfin[dir][b][jcol]) = make_float2(hv[0], hv[1]);
            }
        }

        grid_barrier();
    }

    // final c writeback
#pragma unroll
    for (int ci = 0; ci < 8; ci++) {
        int mt = ci >> 2, rr = (ci >> 1) & 1, jj = ci & 1;
        int b  = mrow * 32 + mt * 16 + rr * 8 + r0;
        int jl = ncol * 8 + 2 * q + jj;
        g_cfin[dir][b][j0 + jl] = c_reg[ci];
    }
}

// ------------------------- HMMA output projection -----------------------------
__device__ __forceinline__ void proj_issue(uint32_t buf, int t,
    const char* pW0, const char* pW1, int kc, int tid)
{
    const int dirc = kc >> 3;
    const char* pA = (const char*)&g_out16[dirc][t][0][0];
    const size_t kb = (size_t)(kc & 7) * 256;
#pragma unroll
    for (int i = 0; i < 8; i++) {
        int idx = tid + 256 * i;
        int kh = idx >> 10, r = (idx >> 3) & 127, seg = idx & 7;
        CPA(buf + kh * 16384 + swz(r * 128 + seg * 16),
            pA + (size_t)r * 2048 + kb + kh * 128 + seg * 16);
    }
    const size_t kbw = (size_t)kc * 256;
#pragma unroll
    for (int i = 0; i < 4; i++) {
        int idx = tid + 256 * i;
        int kh = idx >> 9, r = (idx >> 3) & 63, seg = idx & 7;
        uint32_t so = kh * 8192 + swz(r * 128 + seg * 16);
        size_t go = (size_t)r * 4096 + kbw + kh * 128 + seg * 16;
        CPA(buf + 32768 + so, pW0 + go);
        CPA(buf + 49152 + so, pW1 + go);
    }
    asm volatile("cp.async.commit_group;" ::: "memory");
}

__global__ void __launch_bounds__(256, 1) k_proj_h(
    const float* __restrict__ b_out, float* __restrict__ out)
{
    extern __shared__ __align__(128) char dsm[];
    const uint32_t sb = smem_u32(dsm);

    const int tid  = threadIdx.x;
    const int w    = tid >> 5, lane = tid & 31;
    const int lr   = lane & 15, lh = lane >> 4;
    const int q    = lane & 3,  r0 = lane >> 2;
    const int bid  = blockIdx.x;          // 1024
    const int t    = bid >> 1, vh = bid & 1;
    const int mrow = w >> 1, ncol = w & 1;

    const char* pW0 = (const char*)&g_WoTh[vh * 64][0];
    const char* pW1 = (const char*)&g_WoTl[vh * 64][0];

    float d1[8][4] = {}, d2[8][4] = {};
    proj_issue(sb, t, pW0, pW1, 0, tid);

    for (int kc = 0; kc < 16; kc++) {
        asm volatile("cp.async.wait_group 0;" ::: "memory");
        __syncthreads();
        if (kc < 15)
            proj_issue(sb + ((kc + 1) & 1) * RBUF, t, pW0, pW1, kc + 1, tid);
        const uint32_t base = sb + (kc & 1) * RBUF;
        CHUNK_MATH(base)
    }

#pragma unroll
    for (int mt = 0; mt < 2; mt++) {
#pragma unroll
        for (int rr = 0; rr < 2; rr++) {
            const int b = mrow * 32 + mt * 16 + rr * 8 + r0;
#pragma unroll
            for (int nt = 0; nt < 4; nt++) {
                const int v = vh * 64 + ncol * 32 + nt * 8 + 2 * q;
                float2 bv = *(const float2*)(b_out + v);
                float2 o;
                o.x = d1[mt*4+nt][rr*2+0] + d2[mt*4+nt][rr*2+0] * SC_WI + bv.x;
                o.y = d1[mt*4+nt][rr*2+1] + d2[mt*4+nt][rr*2+1] * SC_WI + bv.y;
                *(float2*)(out + ((size_t)b * Ssz + t) * Vsz + v) = o;
            }
        }
    }
}

// ------------------------- final state writeback ------------------------------
__global__ void k_states(float* __restrict__ out)
{
    int i = blockIdx.x * blockDim.x + threadIdx.x;
    if (i < Bsz * Hsz) {
        int b = i >> 10, j = i & 1023;
        size_t base = (size_t)Bsz * Ssz * Vsz;
        out[base + 0 * Bsz * Hsz + i] = g_hfin[0][b][j];
        out[base + 1 * Bsz * Hsz + i] = g_hfin[1][b][j];
        out[base + 2 * Bsz * Hsz + i] = g_cfin[0][b][j];
        out[base + 3 * Bsz * Hsz + i] = g_cfin[1][b][j];
    }
}

// ---------------------------------------------------------------------------
extern "C" void kernel_launch(void* const* d_in, const int* in_sizes, int n_in,
                              void* d_out, int out_size)
{
    const int*   x     = (const int*)  d_in[0];
    const float* h_f   = (const float*)d_in[1];
    const float* h_b   = (const float*)d_in[2];
    const float* c_f   = (const float*)d_in[3];
    const float* c_b   = (const float*)d_in[4];
    const float* emb   = (const float*)d_in[5];
    const float* W_f   = (const float*)d_in[6];
    const float* b_f   = (const float*)d_in[7];
    const float* W_b   = (const float*)d_in[8];
    const float* b_b   = (const float*)d_in[9];
    const float* W_out = (const float*)d_in[10];
    const float* b_out = (const float*)d_in[11];
    float* out = (float*)d_out;

    static bool attr_done = false;
    if (!attr_done) {
        cudaFuncSetAttribute(k_recurrent,
                             cudaFuncAttributeMaxDynamicSharedMemorySize, SMEM_DYN);
        cudaFuncSetAttribute(k_proj_h,
                             cudaFuncAttributeMaxDynamicSharedMemorySize, SMEM_DYN);
        attr_done = true;
    }

    k_hinit<<<1024, 256>>>(h_f, h_b);
    k_wprep<<<8192, 256>>>(W_f, W_b);
    k_lut<<<64, 256>>>(emb, W_f, b_f, W_b, b_b);
    k_lutperm<<<4096, 256>>>();
    k_woutprep<<<1024, 256>>>(W_out);

    k_recurrent<<<NB, 256, SMEM_DYN>>>(x, c_f, c_b);

    k_proj_h<<<1024, 256, SMEM_DYN>>>(b_out, out);
    if (out_size >= (int)((size_t)Bsz * Ssz * Vsz + 4 * Bsz * Hsz))
        k_states<<<512, 256>>>(out);
}

// round 8
// speedup vs baseline: 4.9308x; 1.5072x over previous
#include <cuda_runtime.h>
#include <cuda_fp16.h>
#include <math.h>
#include <stdint.h>

// ---------------------------------------------------------------------------
// BLSTM: B=128, S=512, H=1024, VOCAB=128
// 1-product fp16 HMMA recurrence (h fp16, W fp16), m32n32 warp tiles,
// k128 chunks, LUT prefetch; 2-product HMMA output projection.
// ---------------------------------------------------------------------------

#define Bsz   128
#define Ssz   512
#define Hsz   1024
#define Vsz   128
#define G4    4096
#define KT    32
#define NB    128

#define SC_W  2048.0f
#define SC_WI (1.0f/2048.0f)

// recurrence buffer: A 32K | Wh 16K = 48 KB ; double buffered = 96 KB
#define RBUF_R    49152
#define SMEM_REC  (2 * RBUF_R)
// projection buffer: A 32K | Wh 16K | Wl 16K = 64 KB ; double = 128 KB
#define RBUF_P    65536
#define SMEM_PROJ (2 * RBUF_P)

typedef unsigned long long u64;
typedef unsigned int u32;

// ------------------------- device scratch -----------------------------------
__device__ float  g_token_gates[2][Vsz][G4];       // LUT original order
__device__ float  g_lutP[2][Vsz][G4];              // LUT permuted (nP)
__device__ __half g_h16[2][2][Bsz][Hsz];           // [dir][parity][b][k]
__device__ __half g_Wh[2][G4][Hsz];                // W^T fp16 (permuted nP)
__device__ __half g_out16[2][Ssz][Bsz][Hsz];       // h history fp16
__device__ __half g_WoTh[Vsz][2 * Hsz];            // W_out^T hi
__device__ __half g_WoTl[Vsz][2 * Hsz];            // W_out^T lo * SC_W
__device__ float  g_hfin[2][Bsz][Hsz];
__device__ float  g_cfin[2][Bsz][Hsz];
__device__ volatile unsigned g_gen;
__device__ unsigned g_count;

// ------------------------- helpers ------------------------------------------
static __device__ __forceinline__ uint32_t smem_u32(const void* p) {
    uint32_t a;
    asm("{ .reg .u64 t; cvta.to.shared.u64 t, %1; cvt.u32.u64 %0, t; }"
        : "=r"(a) : "l"(p));
    return a;
}
static __device__ __forceinline__ uint32_t swz(uint32_t o) {
    return o ^ ((o >> 3) & 0x70);
}
#define CPA(dst, src) \
    asm volatile("cp.async.cg.shared.global [%0], [%1], 16;" \
                 :: "r"(dst), "l"(src) : "memory")

static __device__ __forceinline__ void ldsm4(u32 r[4], u32 addr) {
    asm volatile("ldmatrix.sync.aligned.m8n8.x4.shared.b16 {%0,%1,%2,%3}, [%4];"
                 : "=r"(r[0]), "=r"(r[1]), "=r"(r[2]), "=r"(r[3]) : "r"(addr));
}
static __device__ __forceinline__ void mma_f16(float d[4], const u32 a[4],
                                               u32 b0, u32 b1) {
    asm volatile(
        "mma.sync.aligned.m16n8k16.row.col.f32.f16.f16.f32 "
        "{%0,%1,%2,%3}, {%4,%5,%6,%7}, {%8,%9}, {%0,%1,%2,%3};"
        : "+f"(d[0]), "+f"(d[1]), "+f"(d[2]), "+f"(d[3])
        : "r"(a[0]), "r"(a[1]), "r"(a[2]), "r"(a[3]), "r"(b0), "r"(b1));
}

// ------------------------- grid barrier --------------------------------------
__device__ __forceinline__ void grid_barrier()
{
    __syncthreads();
    if (threadIdx.x == 0) {
        unsigned gen = g_gen;
        __threadfence();
        unsigned t = atomicAdd(&g_count, 1);
        if (t == NB - 1) {
            g_count = 0;
            __threadfence();
            g_gen = gen + 1;
        } else {
            while (g_gen == gen) {}
        }
        __threadfence();
    }
    __syncthreads();
}

// ------------------------- FFMA GEMM core (lut only) -------------------------
__device__ __forceinline__ void gemm_tile_K(
    const float* __restrict__ A, int lda,
    const float* __restrict__ B, int ldb,
    int K, u64 acc[8][4],
    float* As, float* Bs)
{
    const int tid = threadIdx.x;
    const int tx  = tid & 15;
    const int ty  = tid >> 4;

    float4 ra[4], rb[4];
#pragma unroll
    for (int i = 0; i < 4; i++) {
        int c = tid + 256 * i;
        ra[i] = *(const float4*)(A + (size_t)(c >> 3) * lda + ((c & 7) << 2));
        rb[i] = *(const float4*)(B + (size_t)(c >> 5) * ldb + ((c & 31) << 2));
    }
    for (int k0 = 0; k0 < K; k0 += KT) {
        __syncthreads();
#pragma unroll
        for (int i = 0; i < 4; i++) {
            int c = tid + 256 * i;
            *(float4*)(As + (c >> 3) * KT  + ((c & 7)  << 2)) = ra[i];
            *(float4*)(Bs + (c >> 5) * 128 + ((c & 31) << 2)) = rb[i];
        }
        __syncthreads();
        const int k1 = k0 + KT;
        if (k1 < K) {
#pragma unroll
            for (int i = 0; i < 4; i++) {
                int c = tid + 256 * i;
                ra[i] = *(const float4*)(A + (size_t)(c >> 3) * lda + k1 + ((c & 7) << 2));
                rb[i] = *(const float4*)(B + (size_t)(k1 + (c >> 5)) * ldb + ((c & 31) << 2));
            }
        }
#pragma unroll
        for (int k = 0; k < KT; k++) {
            const float* brow = Bs + k * 128 + tx * 8;
            ulonglong2 q0 = *(const ulonglong2*)brow;
            ulonglong2 q1 = *(const ulonglong2*)(brow + 4);
            u64 bp0 = q0.x, bp1 = q0.y, bp2 = q1.x, bp3 = q1.y;
#pragma unroll
            for (int i = 0; i < 8; i++) {
                float a = As[(ty * 8 + i) * KT + k];
                u64 ad;
                asm("mov.b64 %0, {%1, %1};" : "=l"(ad) : "f"(a));
                asm("fma.rn.f32x2 %0, %1, %2, %0;" : "+l"(acc[i][0]) : "l"(ad), "l"(bp0));
                asm("fma.rn.f32x2 %0, %1, %2, %0;" : "+l"(acc[i][1]) : "l"(ad), "l"(bp1));
                asm("fma.rn.f32x2 %0, %1, %2, %0;" : "+l"(acc[i][2]) : "l"(ad), "l"(bp2));
                asm("fma.rn.f32x2 %0, %1, %2, %0;" : "+l"(acc[i][3]) : "l"(ad), "l"(bp3));
            }
        }
    }
}
union F4U { u64 u[2]; float4 v; };

// ------------------------- prep kernels --------------------------------------
__global__ void k_hinit(const float* __restrict__ h_f, const float* __restrict__ h_b)
{
    int i = blockIdx.x * blockDim.x + threadIdx.x;
    if (i < 2 * Bsz * Hsz) {
        int dir = i >> 17, b = (i >> 10) & 127, k = i & 1023;
        g_h16[dir][0][b][k] = __float2half((dir ? h_b : h_f)[b * Hsz + k]);
    }
}

// nP = slice*64 + jh*32 + g*8 + jl3  <->  orig col = g*1024 + slice*16 + jh*8 + jl3
__global__ void __launch_bounds__(256) k_wprep(const float* __restrict__ W_f,
                                               const float* __restrict__ W_b)
{
    int bid   = blockIdx.x;                 // 8192 blocks
    int kblk  = bid & 15;
    int g     = (bid >> 4) & 3;
    int slice = (bid >> 6) & 63;
    int dir   = bid >> 12;
    const float* W = dir ? W_b : W_f;

    int jl = threadIdx.x >> 4;              // 0..15
    int kk = threadIdx.x & 15;
    int col = g * 1024 + slice * 16 + jl;
    int jh = jl >> 3, jl3 = jl & 7;
    int nP  = slice * 64 + jh * 32 + g * 8 + jl3;
#pragma unroll
    for (int r = 0; r < 4; r++) {
        int k = kblk * 64 + kk + r * 16;
        g_Wh[dir][nP][k] = __float2half(W[(size_t)(Hsz + k) * G4 + col]);
    }
}

__global__ void k_lutperm()
{
    int i = blockIdx.x * blockDim.x + threadIdx.x;
    if (i < 2 * Vsz * G4) {
        int d = i >> 19, v = (i >> 12) & 127, nP = i & 4095;
        int slice = nP >> 6, rem = nP & 63;
        int jh = rem >> 5, g = (rem >> 3) & 3, jl3 = rem & 7;
        g_lutP[d][v][nP] =
            g_token_gates[d][v][g * 1024 + slice * 16 + jh * 8 + jl3];
    }
}

__global__ void k_woutprep(const float* __restrict__ W_out)
{
    int i = blockIdx.x * blockDim.x + threadIdx.x;
    if (i < Vsz * 2 * Hsz) {
        int v = i >> 11, k = i & 2047;
        float wv = W_out[(size_t)k * Vsz + v];
        __half hi = __float2half(wv);
        g_WoTh[v][k] = hi;
        g_WoTl[v][k] = __float2half((wv - __half2float(hi)) * SC_W);
    }
}

__global__ void __launch_bounds__(256) k_lut(
    const float* __restrict__ emb,
    const float* __restrict__ W_f, const float* __restrict__ b_f,
    const float* __restrict__ W_b, const float* __restrict__ b_b)
{
    __shared__ __align__(16) float As[128 * KT];
    __shared__ __align__(16) float Bs[KT * 128];
    int dir   = blockIdx.x >> 5;
    int slice = blockIdx.x & 31;
    const float* W    = dir ? W_b : W_f;
    const float* bias = dir ? b_b : b_f;

    u64 acc[8][4] = {};
    gemm_tile_K(emb, Hsz, W + slice * 128, G4, Hsz, acc, As, Bs);

    const int tx = threadIdx.x & 15, ty = threadIdx.x >> 4;
    float* C = &g_token_gates[dir][0][0] + slice * 128;
    float4 bv0 = *(const float4*)(bias + slice * 128 + tx * 8);
    float4 bv1 = *(const float4*)(bias + slice * 128 + tx * 8 + 4);
#pragma unroll
    for (int i = 0; i < 8; i++) {
        int r = ty * 8 + i;
        F4U u0; u0.u[0] = acc[i][0]; u0.u[1] = acc[i][1];
        F4U u1; u1.u[0] = acc[i][2]; u1.u[1] = acc[i][3];
        u0.v.x += bv0.x; u0.v.y += bv0.y; u0.v.z += bv0.z; u0.v.w += bv0.w;
        u1.v.x += bv1.x; u1.v.y += bv1.y; u1.v.z += bv1.z; u1.v.w += bv1.w;
        *(float4*)(C + (size_t)r * G4 + tx * 8)     = u0.v;
        *(float4*)(C + (size_t)r * G4 + tx * 8 + 4) = u1.v;
    }
}

// ------------------------- recurrence staging (A + Wh) -----------------------
__device__ __forceinline__ void rec_issue(uint32_t buf, const char* pA,
    const char* pWh, size_t kb, int tid)
{
#pragma unroll
    for (int i = 0; i < 8; i++) {
        int idx = tid + 256 * i;
        int kh = idx >> 10, r = (idx >> 3) & 127, seg = idx & 7;
        CPA(buf + kh * 16384 + swz(r * 128 + seg * 16),
            pA + (size_t)r * 2048 + kb + kh * 128 + seg * 16);
    }
#pragma unroll
    for (int i = 0; i < 4; i++) {
        int idx = tid + 256 * i;
        int kh = idx >> 9, r = (idx >> 3) & 63, seg = idx & 7;
        CPA(buf + 32768 + kh * 8192 + swz(r * 128 + seg * 16),
            pWh + (size_t)r * 2048 + kb + kh * 128 + seg * 16);
    }
    asm volatile("cp.async.commit_group;" ::: "memory");
}

// 1-product chunk math (recurrence)
#define CHUNK_MATH_1P(base)                                                     \
    _Pragma("unroll")                                                           \
    for (int kk = 0; kk < 8; kk++) {                                            \
        const int kh = kk >> 2;                                                 \
        const uint32_t koff = (kk & 3) * 32 + lh * 16;                          \
        const uint32_t ab = (base) + kh * 16384;                                \
        u32 ah0[4], ah1[4];                                                     \
        ldsm4(ah0, ab + swz((mrow * 32 + lr) * 128 + koff));                    \
        ldsm4(ah1, ab + swz((mrow * 32 + 16 + lr) * 128 + koff));               \
        const uint32_t wb = (base) + 32768 + kh * 8192;                         \
        _Pragma("unroll")                                                       \
        for (int nh = 0; nh < 2; nh++) {                                        \
            u32 wh[4];                                                          \
            uint32_t wro = swz((ncol * 32 + nh * 16 + lr) * 128 + koff);        \
            ldsm4(wh, wb + wro);                                                \
            mma_f16(d1[nh * 2],     ah0, wh[0], wh[2]);                         \
            mma_f16(d1[nh * 2 + 1], ah0, wh[1], wh[3]);                         \
            mma_f16(d1[4 + nh * 2],     ah1, wh[0], wh[2]);                     \
            mma_f16(d1[4 + nh * 2 + 1], ah1, wh[1], wh[3]);                     \
        }                                                                       \
    }

// 2-product chunk math (projection; Wl at +16384 past Wh)
#define CHUNK_MATH_2P(base)                                                     \
    _Pragma("unroll")                                                           \
    for (int kk = 0; kk < 8; kk++) {                                            \
        const int kh = kk >> 2;                                                 \
        const uint32_t koff = (kk & 3) * 32 + lh * 16;                          \
        const uint32_t ab = (base) + kh * 16384;                                \
        u32 ah0[4], ah1[4];                                                     \
        ldsm4(ah0, ab + swz((mrow * 32 + lr) * 128 + koff));                    \
        ldsm4(ah1, ab + swz((mrow * 32 + 16 + lr) * 128 + koff));               \
        const uint32_t wb = (base) + 32768 + kh * 8192;                         \
        _Pragma("unroll")                                                       \
        for (int nh = 0; nh < 2; nh++) {                                        \
            u32 wh[4], wl[4];                                                   \
            uint32_t wro = swz((ncol * 32 + nh * 16 + lr) * 128 + koff);        \
            ldsm4(wh, wb + wro);                                                \
            ldsm4(wl, wb + 16384 + wro);                                        \
            mma_f16(d1[nh * 2],     ah0, wh[0], wh[2]);                         \
            mma_f16(d1[nh * 2 + 1], ah0, wh[1], wh[3]);                         \
            mma_f16(d2[nh * 2],     ah0, wl[0], wl[2]);                         \
            mma_f16(d2[nh * 2 + 1], ah0, wl[1], wl[3]);                         \
            mma_f16(d1[4 + nh * 2],     ah1, wh[0], wh[2]);                     \
            mma_f16(d1[4 + nh * 2 + 1], ah1, wh[1], wh[3]);                     \
            mma_f16(d2[4 + nh * 2],     ah1, wl[0], wl[2]);                     \
            mma_f16(d2[4 + nh * 2 + 1], ah1, wl[1], wl[3]);                     \
        }                                                                       \
    }

// ------------------------- persistent recurrence -----------------------------
__global__ void __launch_bounds__(256, 1) k_recurrent(
    const int* __restrict__ x,
    const float* __restrict__ c_f, const float* __restrict__ c_b)
{
    extern __shared__ __align__(128) char dsm[];
    const uint32_t sb = smem_u32(dsm);

    const int tid  = threadIdx.x;
    const int w    = tid >> 5, lane = tid & 31;
    const int lr   = lane & 15, lh = lane >> 4;
    const int q    = lane & 3,  r0 = lane >> 2;
    const int blk  = blockIdx.x;
    const int dir  = blk >> 6, slice = blk & 63;
    const int n0   = slice * 64, j0 = slice * 16;
    const int mrow = w >> 1, ncol = w & 1;

    float c_reg[8];
    {
        const float* cin = dir ? c_b : c_f;
#pragma unroll
        for (int ci = 0; ci < 8; ci++) {
            int mt = ci >> 2, rr = (ci >> 1) & 1, jj = ci & 1;
            int b  = mrow * 32 + mt * 16 + rr * 8 + r0;
            int jl = ncol * 8 + 2 * q + jj;
            c_reg[ci] = cin[(size_t)b * Hsz + j0 + jl];
        }
    }

    const char* pWh = (const char*)&g_Wh[dir][n0][0];

    for (int s = 0; s < Ssz; s++) {
        const int rp = s & 1;
        const int ts = dir ? (Ssz - 1 - s) : s;
        const char* pA = (const char*)&g_h16[dir][rp][0][0];

        // prefetch LUT gathers for this step (hides L2 latency under GEMM)
        float2 lp[2][2][4];
#pragma unroll
        for (int mt = 0; mt < 2; mt++)
#pragma unroll
            for (int rr = 0; rr < 2; rr++) {
                const int b = mrow * 32 + mt * 16 + rr * 8 + r0;
                const int tok = __ldg(&x[b * Ssz + ts]);
                const float* lutb = &g_lutP[dir][tok][n0 + ncol * 32];
#pragma unroll
                for (int g = 0; g < 4; g++)
                    lp[mt][rr][g] = *(const float2*)(lutb + g * 8 + 2 * q);
            }

        float d1[8][4] = {};
        rec_issue(sb, pA, pWh, 0, tid);

        for (int kc = 0; kc < 8; kc++) {
            asm volatile("cp.async.wait_group 0;" ::: "memory");
            __syncthreads();
            if (kc < 7)
                rec_issue(sb + ((kc + 1) & 1) * RBUF_R, pA, pWh,
                          (size_t)(kc + 1) * 256, tid);
            const uint32_t base = sb + (kc & 1) * RBUF_R;
            CHUNK_MATH_1P(base)
        }

        // ---- epilogue: thread-local LSTM update ----
        const int wp = rp ^ 1;
#pragma unroll
        for (int mt = 0; mt < 2; mt++) {
#pragma unroll
            for (int rr = 0; rr < 2; rr++) {
                const int b = mrow * 32 + mt * 16 + rr * 8 + r0;
                float hv[2];
#pragma unroll
                for (int jj = 0; jj < 2; jj++) {
                    const int ri = rr * 2 + jj;
                    float zi = d1[mt*4+0][ri] + (jj ? lp[mt][rr][0].y : lp[mt][rr][0].x);
                    float zf = d1[mt*4+1][ri] + (jj ? lp[mt][rr][1].y : lp[mt][rr][1].x);
                    float zo = d1[mt*4+2][ri] + (jj ? lp[mt][rr][2].y : lp[mt][rr][2].x);
                    float zg = d1[mt*4+3][ri] + (jj ? lp[mt][rr][3].y : lp[mt][rr][3].x);
                    float ig = 1.f / (1.f + __expf(-zi));
                    float fg = 1.f / (1.f + __expf(-zf));
                    float og = 1.f / (1.f + __expf(-zo));
                    const int ci = mt * 4 + rr * 2 + jj;
                    float cc = fg * c_reg[ci] + ig * tanhf(zg);
                    c_reg[ci] = cc;
                    hv[jj] = og * tanhf(cc);
                }
                __half2 hp = __floats2half2_rn(hv[0], hv[1]);
                const int jcol = j0 + ncol * 8 + 2 * q;
                *(u32*)(&g_h16[dir][wp][b][jcol])   = *(u32*)&hp;
                *(u32*)(&g_out16[dir][ts][b][jcol]) = *(u32*)&hp;
                if (s == Ssz - 1)
                    *(float2*)(&g_hfin[dir][b][jcol]) = make_float2(hv[0], hv[1]);
            }
        }

        grid_barrier();
    }

#pragma unroll
    for (int ci = 0; ci < 8; ci++) {
        int mt = ci >> 2, rr = (ci >> 1) & 1, jj = ci & 1;
        int b  = mrow * 32 + mt * 16 + rr * 8 + r0;
        int jl = ncol * 8 + 2 * q + jj;
        g_cfin[dir][b][j0 + jl] = c_reg[ci];
    }
}

// ------------------------- HMMA output projection -----------------------------
__device__ __forceinline__ void proj_issue(uint32_t buf, int t,
    const char* pW0, const char* pW1, int kc, int tid)
{
    const int dirc = kc >> 3;
    const char* pA = (const char*)&g_out16[dirc][t][0][0];
    const size_t kb = (size_t)(kc & 7) * 256;
#pragma unroll
    for (int i = 0; i < 8; i++) {
        int idx = tid + 256 * i;
        int kh = idx >> 10, r = (idx >> 3) & 127, seg = idx & 7;
        CPA(buf + kh * 16384 + swz(r * 128 + seg * 16),
            pA + (size_t)r * 2048 + kb + kh * 128 + seg * 16);
    }
    const size_t kbw = (size_t)kc * 256;
#pragma unroll
    for (int i = 0; i < 4; i++) {
        int idx = tid + 256 * i;
        int kh = idx >> 9, r = (idx >> 3) & 63, seg = idx & 7;
        uint32_t so = kh * 8192 + swz(r * 128 + seg * 16);
        size_t go = (size_t)r * 4096 + kbw + kh * 128 + seg * 16;
        CPA(buf + 32768 + so, pW0 + go);
        CPA(buf + 49152 + so, pW1 + go);
    }
    asm volatile("cp.async.commit_group;" ::: "memory");
}

__global__ void __launch_bounds__(256, 1) k_proj_h(
    const float* __restrict__ b_out, float* __restrict__ out)
{
    extern __shared__ __align__(128) char dsm[];
    const uint32_t sb = smem_u32(dsm);

    const int tid  = threadIdx.x;
    const int w    = tid >> 5, lane = tid & 31;
    const int lr   = lane & 15, lh = lane >> 4;
    const int q    = lane & 3,  r0 = lane >> 2;
    const int bid  = blockIdx.x;          // 1024
    const int t    = bid >> 1, vh = bid & 1;
    const int mrow = w >> 1, ncol = w & 1;

    const char* pW0 = (const char*)&g_WoTh[vh * 64][0];
    const char* pW1 = (const char*)&g_WoTl[vh * 64][0];

    float d1[8][4] = {}, d2[8][4] = {};
    proj_issue(sb, t, pW0, pW1, 0, tid);

    for (int kc = 0; kc < 16; kc++) {
        asm volatile("cp.async.wait_group 0;" ::: "memory");
        __syncthreads();
        if (kc < 15)
            proj_issue(sb + ((kc + 1) & 1) * RBUF_P, t, pW0, pW1, kc + 1, tid);
        const uint32_t base = sb + (kc & 1) * RBUF_P;
        CHUNK_MATH_2P(base)
    }

#pragma unroll
    for (int mt = 0; mt < 2; mt++) {
#pragma unroll
        for (int rr = 0; rr < 2; rr++) {
            const int b = mrow * 32 + mt * 16 + rr * 8 + r0;
#pragma unroll
            for (int nt = 0; nt < 4; nt++) {
                const int v = vh * 64 + ncol * 32 + nt * 8 + 2 * q;
                float2 bv = *(const float2*)(b_out + v);
                float2 o;
                o.x = d1[mt*4+nt][rr*2+0] + d2[mt*4+nt][rr*2+0] * SC_WI + bv.x;
                o.y = d1[mt*4+nt][rr*2+1] + d2[mt*4+nt][rr*2+1] * SC_WI + bv.y;
                *(float2*)(out + ((size_t)b * Ssz + t) * Vsz + v) = o;
            }
        }
    }
}

// ------------------------- final state writeback ------------------------------
__global__ void k_states(float* __restrict__ out)
{
    int i = blockIdx.x * blockDim.x + threadIdx.x;
    if (i < Bsz * Hsz) {
        int b = i >> 10, j = i & 1023;
        size_t base = (size_t)Bsz * Ssz * Vsz;
        out[base + 0 * Bsz * Hsz + i] = g_hfin[0][b][j];
        out[base + 1 * Bsz * Hsz + i] = g_hfin[1][b][j];
        out[base + 2 * Bsz * Hsz + i] = g_cfin[0][b][j];
        out[base + 3 * Bsz * Hsz + i] = g_cfin[1][b][j];
    }
}

// ---------------------------------------------------------------------------
extern "C" void kernel_launch(void* const* d_in, const int* in_sizes, int n_in,
                              void* d_out, int out_size)
{
    const int*   x     = (const int*)  d_in[0];
    const float* h_f   = (const float*)d_in[1];
    const float* h_b   = (const float*)d_in[2];
    const float* c_f   = (const float*)d_in[3];
    const float* c_b   = (const float*)d_in[4];
    const float* emb   = (const float*)d_in[5];
    const float* W_f   = (const float*)d_in[6];
    const float* b_f   = (const float*)d_in[7];
    const float* W_b   = (const float*)d_in[8];
    const float* b_b   = (const float*)d_in[9];
    const float* W_out = (const float*)d_in[10];
    const float* b_out = (const float*)d_in[11];
    float* out = (float*)d_out;

    static bool attr_done = false;
    if (!attr_done) {
        cudaFuncSetAttribute(k_recurrent,
                             cudaFuncAttributeMaxDynamicSharedMemorySize, SMEM_REC);
        cudaFuncSetAttribute(k_proj_h,
                             cudaFuncAttributeMaxDynamicSharedMemorySize, SMEM_PROJ);
        attr_done = true;
    }

    k_hinit<<<1024, 256>>>(h_f, h_b);
    k_wprep<<<8192, 256>>>(W_f, W_b);
    k_lut<<<64, 256>>>(emb, W_f, b_f, W_b, b_b);
    k_lutperm<<<4096, 256>>>();
    k_woutprep<<<1024, 256>>>(W_out);

    k_recurrent<<<NB, 256, SMEM_REC>>>(x, c_f, c_b);

    k_proj_h<<<1024, 256, SMEM_PROJ>>>(b_out, out);
    if (out_size >= (int)((size_t)Bsz * Ssz * Vsz + 4 * Bsz * Hsz))
        k_states<<<512, 256>>>(out);
}